// round 4
// baseline (speedup 1.0000x reference)
#include <cuda_runtime.h>
#include <cstdint>
#include <cstddef>

typedef unsigned long long ull;

// ---------- packed f32x2 helpers (Blackwell sm_103a) ----------
__device__ __forceinline__ ull pk2(float a, float b) {
    ull r; asm("mov.b64 %0, {%1, %2};" : "=l"(r) : "f"(a), "f"(b)); return r;
}
__device__ __forceinline__ float2 up2(ull v) {
    float2 f; asm("mov.b64 {%0, %1}, %2;" : "=f"(f.x), "=f"(f.y) : "l"(v)); return f;
}
__device__ __forceinline__ void fma2(ull& d, ull a, ull b) {
    asm("fma.rn.f32x2 %0, %1, %2, %0;" : "+l"(d) : "l"(a), "l"(b));
}
__device__ __forceinline__ void mul2(ull& d, ull a) {
    asm("mul.rn.f32x2 %0, %0, %1;" : "+l"(d) : "l"(a));
}

#define BN   4
#define CH   64
#define NPIX 4096   // 64*64

// ---------- scratch (no cudaMalloc allowed) ----------
__device__ float g_Q [BN*CH*NPIX];
__device__ float g_rk[BN*CH*NPIX];
__device__ float g_rv[BN*CH*NPIX];
__device__ float g_ik[BN*CH*NPIX];
__device__ float g_iv[BN*CH*NPIX];
__device__ float g_rr[BN*CH*NPIX];
__device__ float g_ir[BN*CH*NPIX];

// ============================================================
// conv3x3 + BN-affine + ReLU.  16x16 spatial tile, 16 out-chans
// per block, f32x2 register accumulation (8 packed pairs).
// grid: (4, 4, NCONV*B*4)  block: 256
// ============================================================
struct CArg { const float* inA; const float* inB; const float* w;
              const float* s; const float* bb; float* out; };
struct CPack { CArg c[4]; };

template<int CIN>
__global__ void __launch_bounds__(256) conv_k(CPack P) {
    __shared__ float tile[18*20];
    __shared__ float wsm[9*16];
    const int tid = threadIdx.x;
    const int tx = tid & 15, ty = tid >> 4;
    const int z = blockIdx.z;
    const int conv = z >> 4;
    const int b    = (z >> 2) & 3;
    const int ocb  = (z & 3) << 4;
    const CArg a = P.c[conv];
    const int ox0 = blockIdx.x << 4, oy0 = blockIdx.y << 4;
    const int ox = ox0 + tx, oy = oy0 + ty;

    ull acc[8];
#pragma unroll
    for (int p = 0; p < 8; p++) acc[p] = 0ull;

    for (int ci = 0; ci < CIN; ci++) {
        const float* src = a.inA; int cc = ci;
        if (CIN == 128 && ci >= 64) { src = a.inB; cc = ci - 64; }
        __syncthreads();
        const float* sp = src + ((size_t)b * 64 + cc) * 4096;
        for (int i = tid; i < 324; i += 256) {
            int r = i / 18, c2 = i - r * 18;
            int iy = oy0 - 1 + r, ix = ox0 - 1 + c2;
            float v = 0.f;
            if ((unsigned)iy < 64u && (unsigned)ix < 64u) v = sp[iy * 64 + ix];
            tile[r * 20 + c2] = v;
        }
        if (tid < 144) {
            int o = tid & 15, k = tid >> 4;
            wsm[k * 16 + o] = a.w[((size_t)(ocb + o) * CIN + ci) * 9 + k];
        }
        __syncthreads();

        float v[9];
#pragma unroll
        for (int ky = 0; ky < 3; ky++)
#pragma unroll
            for (int kx = 0; kx < 3; kx++)
                v[ky * 3 + kx] = tile[(ty + ky) * 20 + tx + kx];
#pragma unroll
        for (int k = 0; k < 9; k++) {
            ull vv = pk2(v[k], v[k]);
#pragma unroll
            for (int p = 0; p < 8; p++)
                fma2(acc[p], vv, *(const ull*)(wsm + k * 16 + 2 * p));
        }
    }

#pragma unroll
    for (int p = 0; p < 8; p++) {
        float2 o2 = up2(acc[p]);
#pragma unroll
        for (int j = 0; j < 2; j++) {
            int oc = ocb + 2 * p + j;
            float val = (j ? o2.y : o2.x) * a.s[oc] + a.bb[oc];
            val = fmaxf(val, 0.f);
            a.out[(((size_t)b * 64 + oc) * 64 + oy) * 64 + ox] = val;
        }
    }
}

// ============================================================
// Flash attention:  out[c,m] = sum_n softmax_n(Aq_m . Kq_n) V[c,n]
// 64-query tile per block, loop over 64 key tiles of 64.
// 256 threads, each owns a 4(m) x 4(c) f32x2-packed accumulator.
// grid: (64 mtiles, B, 2 attentions)  dyn smem 68352 B
// ============================================================
#define VP 68   // padded pitch for Vt / Pt (16B-aligned, conflict-light)

__global__ void __launch_bounds__(256) attn_k(const float* __restrict__ x,
                                              const float* __restrict__ y,
                                              const float* __restrict__ g1,
                                              const float* __restrict__ g2) {
    extern __shared__ float sm[];
    float* Qs  = sm;                 // [c][m]  64x64   (attn queries = conv K out)
    float* Ks  = Qs + 64 * 64;       // [c][n]  64x64   (attn keys    = conv Q out)
    float* Vt  = Ks + 64 * 64;       // [n][c]  64xVP
    float* Pt  = Vt + 64 * VP;       // [n][m]  64xVP   scores -> probs
    float* Mrow = Pt + 64 * VP;      // 64 running max
    float* Lrow = Mrow + 64;         // 64 running sum
    float* Srow = Lrow + 64;         // 64 per-iter rescale

    const int tid = threadIdx.x;
    const int tm = tid & 15, tn = tid >> 4;
    const int mt = blockIdx.x, b = blockIdx.y, a = blockIdx.z;
    const int m0 = mt * 64;

    const size_t boff = (size_t)b * CH * NPIX;
    const float* Aq  = (a ? g_ik : g_rk) + boff;
    const float* Av  = (a ? g_iv : g_rv) + boff;
    const float* Kq  = g_Q + boff;
    const float* res = (a ? x : y) + boff;
    float* outp      = (a ? g_ir : g_rr) + boff;
    const float gamma = a ? g2[0] : g1[0];

    // load query tile [c][m0..m0+63]
    for (int i = tid; i < 64 * 64; i += 256) {
        int c = i >> 6, mi = i & 63;
        Qs[i] = Aq[(size_t)c * NPIX + m0 + mi];
    }
    if (tid < 64) { Mrow[tid] = -1e30f; Lrow[tid] = 0.f; }

    ull O[4][2];
#pragma unroll
    for (int i = 0; i < 4; i++) { O[i][0] = 0ull; O[i][1] = 0ull; }
    __syncthreads();

    for (int nt = 0; nt < 64; nt++) {
        const int n0 = nt * 64;
        // load key tile [c][n] and V transposed [n][c]
        for (int i = tid; i < 64 * 64; i += 256) {
            int c = i >> 6, nn = i & 63;
            float kv = Kq[(size_t)c * NPIX + n0 + nn];
            float vv = Av[(size_t)c * NPIX + n0 + nn];
            Ks[i] = kv;
            Vt[nn * VP + c] = vv;
        }
        __syncthreads();

        // ---- S = Aq^T Kq  (4x4 per thread, f32x2 packed) ----
        ull S[4][2];
#pragma unroll
        for (int i = 0; i < 4; i++) { S[i][0] = 0ull; S[i][1] = 0ull; }
#pragma unroll 8
        for (int k = 0; k < 64; k++) {
            float4 q4 = *(const float4*)(Qs + k * 64 + tm * 4);
            ulonglong2 kk = *(const ulonglong2*)(Ks + k * 64 + tn * 4);
            ull q0 = pk2(q4.x, q4.x), q1 = pk2(q4.y, q4.y);
            ull q2 = pk2(q4.z, q4.z), q3 = pk2(q4.w, q4.w);
            fma2(S[0][0], q0, kk.x); fma2(S[0][1], q0, kk.y);
            fma2(S[1][0], q1, kk.x); fma2(S[1][1], q1, kk.y);
            fma2(S[2][0], q2, kk.x); fma2(S[2][1], q2, kk.y);
            fma2(S[3][0], q3, kk.x); fma2(S[3][1], q3, kk.y);
        }
        // write raw scores transposed: Pt[n][m]
#pragma unroll
        for (int i = 0; i < 4; i++) {
            float2 a0 = up2(S[i][0]), a1 = up2(S[i][1]);
            int m = tm * 4 + i;
            Pt[(tn * 4 + 0) * VP + m] = a0.x;
            Pt[(tn * 4 + 1) * VP + m] = a0.y;
            Pt[(tn * 4 + 2) * VP + m] = a1.x;
            Pt[(tn * 4 + 3) * VP + m] = a1.y;
        }
        __syncthreads();

        // ---- online softmax, warp w owns rows w*8..w*8+7 ----
        {
            const int lane = tid & 31, wrp = tid >> 5;
            for (int rr = 0; rr < 8; rr++) {
                int r = wrp * 8 + rr;
                float s0 = Pt[lane * VP + r];
                float s1 = Pt[(lane + 32) * VP + r];
                float mx = fmaxf(s0, s1);
#pragma unroll
                for (int o = 16; o > 0; o >>= 1)
                    mx = fmaxf(mx, __shfl_xor_sync(0xffffffffu, mx, o));
                float mold = Mrow[r];
                float mnew = fmaxf(mold, mx);
                float p0 = __expf(s0 - mnew), p1 = __expf(s1 - mnew);
                Pt[lane * VP + r] = p0;
                Pt[(lane + 32) * VP + r] = p1;
                float sum = p0 + p1;
#pragma unroll
                for (int o = 16; o > 0; o >>= 1)
                    sum += __shfl_xor_sync(0xffffffffu, sum, o);
                if (lane == 0) {
                    float sc = __expf(mold - mnew);
                    Lrow[r] = Lrow[r] * sc + sum;
                    Mrow[r] = mnew;
                    Srow[r] = sc;
                }
            }
        }
        __syncthreads();

        // ---- rescale accumulator, then O += P V^T ----
#pragma unroll
        for (int i = 0; i < 4; i++) {
            float sc = Srow[tm * 4 + i];
            ull s2 = pk2(sc, sc);
            mul2(O[i][0], s2); mul2(O[i][1], s2);
        }
#pragma unroll 4
        for (int n = 0; n < 64; n++) {
            float4 p4 = *(const float4*)(Pt + n * VP + tm * 4);
            ulonglong2 vv = *(const ulonglong2*)(Vt + n * VP + tn * 4);
            ull p0 = pk2(p4.x, p4.x), p1 = pk2(p4.y, p4.y);
            ull p2 = pk2(p4.z, p4.z), p3 = pk2(p4.w, p4.w);
            fma2(O[0][0], p0, vv.x); fma2(O[0][1], p0, vv.y);
            fma2(O[1][0], p1, vv.x); fma2(O[1][1], p1, vv.y);
            fma2(O[2][0], p2, vv.x); fma2(O[2][1], p2, vv.y);
            fma2(O[3][0], p3, vv.x); fma2(O[3][1], p3, vv.y);
        }
        __syncthreads();
    }

    // ---- epilogue: normalize, gamma-scale, residual add ----
#pragma unroll
    for (int i = 0; i < 4; i++) {
        int row = tm * 4 + i;
        float inv = 1.0f / Lrow[row];
        float2 a0 = up2(O[i][0]), a1 = up2(O[i][1]);
        float vals[4] = {a0.x, a0.y, a1.x, a1.y};
        int m = m0 + row;
#pragma unroll
        for (int j = 0; j < 4; j++) {
            size_t idx = (size_t)(tn * 4 + j) * NPIX + m;
            outp[idx] = gamma * (vals[j] * inv) + res[idx];
        }
    }
}

// ============================================================
// launch
// ============================================================
#define ATT_SMEM (size_t)((64*64*2 + 64*VP*2 + 64*3) * 4)

extern "C" void kernel_launch(void* const* d_in, const int* in_sizes, int n_in,
                              void* d_out, int out_size) {
    const float* x    = (const float*)d_in[0];
    const float* y    = (const float*)d_in[1];
    const float* q_w  = (const float*)d_in[2];
    const float* q_s  = (const float*)d_in[3];
    const float* q_b  = (const float*)d_in[4];
    const float* rk_w = (const float*)d_in[5];
    const float* rk_s = (const float*)d_in[6];
    const float* rk_b = (const float*)d_in[7];
    const float* rv_w = (const float*)d_in[8];
    const float* rv_s = (const float*)d_in[9];
    const float* rv_b = (const float*)d_in[10];
    const float* ik_w = (const float*)d_in[11];
    const float* ik_s = (const float*)d_in[12];
    const float* ik_b = (const float*)d_in[13];
    const float* iv_w = (const float*)d_in[14];
    const float* iv_s = (const float*)d_in[15];
    const float* iv_b = (const float*)d_in[16];
    const float* sr_w = (const float*)d_in[17];
    const float* sr_s = (const float*)d_in[18];
    const float* sr_b = (const float*)d_in[19];
    const float* g1   = (const float*)d_in[20];
    const float* g2   = (const float*)d_in[21];
    float* out = (float*)d_out;

    float *pQ, *prk, *prv, *pik, *piv, *prr, *pir;
    cudaGetSymbolAddress((void**)&pQ,  g_Q);
    cudaGetSymbolAddress((void**)&prk, g_rk);
    cudaGetSymbolAddress((void**)&prv, g_rv);
    cudaGetSymbolAddress((void**)&pik, g_ik);
    cudaGetSymbolAddress((void**)&piv, g_iv);
    cudaGetSymbolAddress((void**)&prr, g_rr);
    cudaGetSymbolAddress((void**)&pir, g_ir);

    cudaFuncSetAttribute(attn_k, cudaFuncAttributeMaxDynamicSharedMemorySize,
                         (int)ATT_SMEM);

    // 1) Q = conv(concat(x,y))
    CPack pq = {};
    pq.c[0] = { x, y, q_w, q_s, q_b, pQ };
    conv_k<128><<<dim3(4, 4, 16), 256>>>(pq);

    // 2) the four 64-channel K/V convs in one launch
    CPack pk = {};
    pk.c[0] = { x, nullptr, rk_w, rk_s, rk_b, prk };
    pk.c[1] = { x, nullptr, rv_w, rv_s, rv_b, prv };
    pk.c[2] = { y, nullptr, ik_w, ik_s, ik_b, pik };
    pk.c[3] = { y, nullptr, iv_w, iv_s, iv_b, piv };
    conv_k<64><<<dim3(4, 4, 64), 256>>>(pk);

    // 3) both attentions + gamma + residual
    attn_k<<<dim3(64, 4, 2), 256, ATT_SMEM>>>(x, y, g1, g2);

    // 4) out = conv(concat(rgb_refine, inf_refine))
    CPack ps = {};
    ps.c[0] = { prr, pir, sr_w, sr_s, sr_b, out };
    conv_k<128><<<dim3(4, 4, 16), 256>>>(ps);
}

// round 6
// speedup vs baseline: 1.1479x; 1.1479x over previous
#include <cuda_runtime.h>
#include <cuda_bf16.h>
#include <cstdint>
#include <cstddef>

typedef unsigned long long ull;
typedef uint32_t u32;

#define BN 4
#define CH 64
#define NPIX 4096

// ---------- scratch ----------
__device__ float g_Q [BN*CH*NPIX];
__device__ float g_rk[BN*CH*NPIX];
__device__ float g_rv[BN*CH*NPIX];
__device__ float g_ik[BN*CH*NPIX];
__device__ float g_iv[BN*CH*NPIX];
__device__ float g_rr[BN*CH*NPIX];
__device__ float g_ir[BN*CH*NPIX];

// ---------- f32x2 helpers (conv) ----------
__device__ __forceinline__ ull pk2(float a, float b) {
    ull r; asm("mov.b64 %0, {%1, %2};" : "=l"(r) : "f"(a), "f"(b)); return r;
}
__device__ __forceinline__ float2 up2(ull v) {
    float2 f; asm("mov.b64 {%0, %1}, %2;" : "=f"(f.x), "=f"(f.y) : "l"(v)); return f;
}
__device__ __forceinline__ void fma2(ull& d, ull a, ull b) {
    asm("fma.rn.f32x2 %0, %1, %2, %0;" : "+l"(d) : "l"(a), "l"(b));
}

// ============================================================
// conv3x3+BN+ReLU, 16x16 tile, 16 oc/block, 4 in-chans/stage
// ============================================================
struct CArg { const float* inA; const float* inB; const float* w;
              const float* s; const float* bb; float* out; };
struct CPack { CArg c[4]; };

template<int CIN>
__global__ void __launch_bounds__(256) conv_k(CPack P) {
    __shared__ float tile[4][18*20];
    __shared__ float wsm[4][9*16];
    const int tid = threadIdx.x;
    const int tx = tid & 15, ty = tid >> 4;
    const int z = blockIdx.z;
    const CArg a = P.c[z >> 4];
    const int b   = (z >> 2) & 3;
    const int ocb = (z & 3) << 4;
    const int ox0 = blockIdx.x << 4, oy0 = blockIdx.y << 4;
    const int ox = ox0 + tx, oy = oy0 + ty;

    ull acc[8];
#pragma unroll
    for (int p = 0; p < 8; p++) acc[p] = 0ull;

    for (int c0 = 0; c0 < CIN; c0 += 4) {
        __syncthreads();
        for (int i = tid; i < 4*324; i += 256) {
            int pl = i / 324, r2 = i - pl * 324;
            int r = r2 / 18, c2 = r2 - r * 18;
            int ci = c0 + pl;
            const float* src = a.inA; int cc = ci;
            if (CIN == 128 && ci >= 64) { src = a.inB; cc = ci - 64; }
            int iy = oy0 - 1 + r, ix = ox0 - 1 + c2;
            float v = 0.f;
            if ((unsigned)iy < 64u && (unsigned)ix < 64u)
                v = src[((size_t)b * 64 + cc) * 4096 + iy * 64 + ix];
            tile[pl][r * 20 + c2] = v;
        }
        for (int i = tid; i < 576; i += 256) {
            int o = i / 36, j = i - o * 36;
            int pl = j / 9, k = j - pl * 9;
            wsm[pl][k * 16 + o] = a.w[((size_t)(ocb + o) * CIN + c0 + pl) * 9 + k];
        }
        __syncthreads();
#pragma unroll
        for (int pl = 0; pl < 4; pl++) {
            float v[9];
#pragma unroll
            for (int ky = 0; ky < 3; ky++)
#pragma unroll
                for (int kx = 0; kx < 3; kx++)
                    v[ky * 3 + kx] = tile[pl][(ty + ky) * 20 + tx + kx];
#pragma unroll
            for (int k = 0; k < 9; k++) {
                ull vv = pk2(v[k], v[k]);
#pragma unroll
                for (int p = 0; p < 8; p++)
                    fma2(acc[p], vv, *(const ull*)(&wsm[pl][k * 16 + 2 * p]));
            }
        }
    }
#pragma unroll
    for (int p = 0; p < 8; p++) {
        float2 o2 = up2(acc[p]);
#pragma unroll
        for (int j = 0; j < 2; j++) {
            int oc = ocb + 2 * p + j;
            float val = fmaxf((j ? o2.y : o2.x) * a.s[oc] + a.bb[oc], 0.f);
            a.out[(((size_t)b * 64 + oc) * 64 + oy) * 64 + ox] = val;
        }
    }
}

// ============================================================
// warp-mma helpers
// ============================================================
__device__ __forceinline__ u32 cvt2bf(float hi, float lo) {   // {lo16=lo, hi16=hi}
    u32 r; asm("cvt.rn.bf16x2.f32 %0, %1, %2;" : "=r"(r) : "f"(hi), "f"(lo)); return r;
}
__device__ __forceinline__ float lo16f(u32 u) { return __uint_as_float(u << 16); }
__device__ __forceinline__ float hi16f(u32 u) { return __uint_as_float(u & 0xFFFF0000u); }

#define MMA(d, a, b0_, b1_) \
    asm volatile("mma.sync.aligned.m16n8k16.row.col.f32.bf16.bf16.f32 " \
        "{%0,%1,%2,%3}, {%4,%5,%6,%7}, {%8,%9}, {%0,%1,%2,%3};" \
        : "+f"((d)[0]), "+f"((d)[1]), "+f"((d)[2]), "+f"((d)[3]) \
        : "r"((a)[0]), "r"((a)[1]), "r"((a)[2]), "r"((a)[3]), "r"(b0_), "r"(b1_))

// smem layout (bytes)
#define QS_OFF 0u            // 64 x 68 fp32 stage          17408
#define KH_OFF 17408u        // 64n x 72c bf16               9216
#define KL_OFF 26624u
#define VH_OFF 35840u        // 64c x 72n bf16
#define VL_OFF 45056u
#define ATT_SMEM 54272u
#define PITCH 72             // bf16 elems per row (144 B)

// ============================================================
// flash attention, warp mma, split-bf16 x3.
// grid (64 mtiles, 4 b, 2 a), 128 threads (4 warps x 16 rows)
// ============================================================
__global__ void __launch_bounds__(128) attn_k(const float* __restrict__ x,
                                              const float* __restrict__ y,
                                              const float* __restrict__ g1,
                                              const float* __restrict__ g2) {
    extern __shared__ char smc[];
    float* Qs = (float*)(smc + QS_OFF);
    const int tid = threadIdx.x;
    const int w = tid >> 5, lane = tid & 31;
    const int qr = lane >> 2, qc2 = (lane & 3) * 2;
    const int m0 = blockIdx.x * 64, b = blockIdx.y, a = blockIdx.z;

    const size_t boff = (size_t)b * CH * NPIX;
    const float* Aq  = (a ? g_ik : g_rk) + boff;   // attention queries (rows)
    const float* Av  = (a ? g_iv : g_rv) + boff;   // values
    const float* Kq  = g_Q + boff;                 // attention keys
    const float* res = (a ? x : y) + boff;
    float* outp      = (a ? g_ir : g_rr) + boff;
    const float gamma = a ? g2[0] : g1[0];

    // ---- stage Q tile [m][c] fp32 ----
    for (int i = tid; i < 4096; i += 128) {
        int m = i & 63, c = i >> 6;
        Qs[m * 68 + c] = Aq[(size_t)c * NPIX + m0 + m];
    }
    __syncthreads();

    // ---- Q fragments (hi/lo bf16), row-major A, held in regs ----
    u32 ah[4][4], al[4][4];
    const int r0 = w * 16 + qr;
#pragma unroll
    for (int j = 0; j < 4; j++) {
        int c0 = j * 16 + qc2;
        float2 f0 = *(float2*)(Qs + r0 * 68 + c0);
        float2 f1 = *(float2*)(Qs + (r0 + 8) * 68 + c0);
        float2 f2 = *(float2*)(Qs + r0 * 68 + c0 + 8);
        float2 f3 = *(float2*)(Qs + (r0 + 8) * 68 + c0 + 8);
        float2 fs[4] = { f0, f1, f2, f3 };
#pragma unroll
        for (int r = 0; r < 4; r++) {
            u32 h = cvt2bf(fs[r].y, fs[r].x);
            ah[j][r] = h;
            al[j][r] = cvt2bf(fs[r].y - hi16f(h), fs[r].x - lo16f(h));
        }
    }

    float O[8][4];
#pragma unroll
    for (int f = 0; f < 8; f++)
#pragma unroll
        for (int r = 0; r < 4; r++) O[f][r] = 0.f;
    float M0 = -1e30f, M1 = -1e30f, L0 = 0.f, L1 = 0.f;

    for (int nt = 0; nt < 64; nt++) {
        const int n0 = nt * 64;
        __syncthreads();
        // ---- fill K (transposed, [n][c]) and V (natural, [c][n]) hi/lo ----
        for (int i = tid; i < 4096; i += 128) {
            if (i < 2048) {                 // K: pair over c
                int n = i & 63, cp = i >> 6;
                float f0 = Kq[(size_t)(2 * cp) * NPIX + n0 + n];
                float f1 = Kq[(size_t)(2 * cp + 1) * NPIX + n0 + n];
                u32 h = cvt2bf(f1, f0);
                u32 l = cvt2bf(f1 - hi16f(h), f0 - lo16f(h));
                ((u32*)(smc + KH_OFF))[n * (PITCH/2) + cp] = h;
                ((u32*)(smc + KL_OFF))[n * (PITCH/2) + cp] = l;
            } else {                        // V: pair over n
                int i2 = i - 2048;
                int np = i2 & 31, c = i2 >> 5;
                float2 f = *(const float2*)(Av + (size_t)c * NPIX + n0 + 2 * np);
                u32 h = cvt2bf(f.y, f.x);
                u32 l = cvt2bf(f.y - hi16f(h), f.x - lo16f(h));
                ((u32*)(smc + VH_OFF))[c * (PITCH/2) + np] = h;
                ((u32*)(smc + VL_OFF))[c * (PITCH/2) + np] = l;
            }
        }
        __syncthreads();

        // ---- S = Q K^T  (16x64 per warp), 3-term split ----
        float S[8][4];
#pragma unroll
        for (int f = 0; f < 8; f++)
#pragma unroll
            for (int r = 0; r < 4; r++) S[f][r] = 0.f;
#pragma unroll
        for (int f = 0; f < 8; f++) {
            const char* kb = smc + ((f * 8 + qr) * PITCH + qc2) * 2;
#pragma unroll
            for (int j = 0; j < 4; j++) {
                u32 kh0 = *(const u32*)(kb + KH_OFF + j * 32);
                u32 kh1 = *(const u32*)(kb + KH_OFF + j * 32 + 16);
                u32 kl0 = *(const u32*)(kb + KL_OFF + j * 32);
                u32 kl1 = *(const u32*)(kb + KL_OFF + j * 32 + 16);
                MMA(S[f], ah[j], kh0, kh1);
                MMA(S[f], al[j], kh0, kh1);
                MMA(S[f], ah[j], kl0, kl1);
            }
        }

        // ---- online softmax (rows r0 = qr, r1 = qr+8 within warp tile) ----
        float mx0 = -1e30f, mx1 = -1e30f;
#pragma unroll
        for (int f = 0; f < 8; f++) {
            mx0 = fmaxf(mx0, fmaxf(S[f][0], S[f][1]));
            mx1 = fmaxf(mx1, fmaxf(S[f][2], S[f][3]));
        }
        mx0 = fmaxf(mx0, __shfl_xor_sync(0xffffffffu, mx0, 1));
        mx0 = fmaxf(mx0, __shfl_xor_sync(0xffffffffu, mx0, 2));
        mx1 = fmaxf(mx1, __shfl_xor_sync(0xffffffffu, mx1, 1));
        mx1 = fmaxf(mx1, __shfl_xor_sync(0xffffffffu, mx1, 2));
        float mn0 = fmaxf(M0, mx0), mn1 = fmaxf(M1, mx1);
        float sc0 = __expf(M0 - mn0), sc1 = __expf(M1 - mn1);
        M0 = mn0; M1 = mn1;
        float s0 = 0.f, s1 = 0.f;
#pragma unroll
        for (int f = 0; f < 8; f++) {
            S[f][0] = __expf(S[f][0] - M0); S[f][1] = __expf(S[f][1] - M0);
            S[f][2] = __expf(S[f][2] - M1); S[f][3] = __expf(S[f][3] - M1);
            s0 += S[f][0] + S[f][1];
            s1 += S[f][2] + S[f][3];
        }
        s0 += __shfl_xor_sync(0xffffffffu, s0, 1);
        s0 += __shfl_xor_sync(0xffffffffu, s0, 2);
        s1 += __shfl_xor_sync(0xffffffffu, s1, 1);
        s1 += __shfl_xor_sync(0xffffffffu, s1, 2);
        L0 = L0 * sc0 + s0;
        L1 = L1 * sc1 + s1;
#pragma unroll
        for (int f = 0; f < 8; f++) {
            O[f][0] *= sc0; O[f][1] *= sc0;
            O[f][2] *= sc1; O[f][3] *= sc1;
        }

        // ---- O += P V^T : P fragments built in-register from S ----
#pragma unroll
        for (int j2 = 0; j2 < 4; j2++) {
            u32 ph[4], pl[4];
#pragma unroll
            for (int h2 = 0; h2 < 2; h2++) {   // h2=0: rows qr (c0,c1); 1: qr+8 (c2,c3)
                float p0a = S[2*j2][2*h2], p1a = S[2*j2][2*h2+1];
                float p0b = S[2*j2+1][2*h2], p1b = S[2*j2+1][2*h2+1];
                u32 hA = cvt2bf(p1a, p0a);
                u32 hB = cvt2bf(p1b, p0b);
                ph[h2]     = hA;   // a0/a1 : k 0-7  (frag 2j2)
                ph[h2 + 2] = hB;   // a2/a3 : k 8-15 (frag 2j2+1)
                pl[h2]     = cvt2bf(p1a - hi16f(hA), p0a - lo16f(hA));
                pl[h2 + 2] = cvt2bf(p1b - hi16f(hB), p0b - lo16f(hB));
            }
            const char* vb = smc + (qr * PITCH + j2 * 16 + qc2) * 2;
#pragma unroll
            for (int fc = 0; fc < 8; fc++) {
                u32 vh0 = *(const u32*)(vb + VH_OFF + fc * 8 * PITCH * 2);
                u32 vh1 = *(const u32*)(vb + VH_OFF + fc * 8 * PITCH * 2 + 16);
                u32 vl0 = *(const u32*)(vb + VL_OFF + fc * 8 * PITCH * 2);
                u32 vl1 = *(const u32*)(vb + VL_OFF + fc * 8 * PITCH * 2 + 16);
                MMA(O[fc], ph, vh0, vh1);
                MMA(O[fc], pl, vh0, vh1);
                MMA(O[fc], ph, vl0, vl1);
            }
        }
    }

    // ---- epilogue: normalize, gamma, residual; out[c][m] ----
    float i0 = 1.0f / L0, i1 = 1.0f / L1;
    const int mA = m0 + r0, mB = mA + 8;
#pragma unroll
    for (int fc = 0; fc < 8; fc++) {
        int c0 = fc * 8 + qc2;
        size_t iA0 = (size_t)c0 * NPIX + mA;
        size_t iA1 = (size_t)(c0 + 1) * NPIX + mA;
        outp[iA0] = gamma * (O[fc][0] * i0) + res[iA0];
        outp[iA1] = gamma * (O[fc][1] * i0) + res[iA1];
        size_t iB0 = (size_t)c0 * NPIX + mB;
        size_t iB1 = (size_t)(c0 + 1) * NPIX + mB;
        outp[iB0] = gamma * (O[fc][2] * i1) + res[iB0];
        outp[iB1] = gamma * (O[fc][3] * i1) + res[iB1];
    }
}

// ============================================================
extern "C" void kernel_launch(void* const* d_in, const int* in_sizes, int n_in,
                              void* d_out, int out_size) {
    const float* x    = (const float*)d_in[0];
    const float* y    = (const float*)d_in[1];
    const float* q_w  = (const float*)d_in[2];
    const float* q_s  = (const float*)d_in[3];
    const float* q_b  = (const float*)d_in[4];
    const float* rk_w = (const float*)d_in[5];
    const float* rk_s = (const float*)d_in[6];
    const float* rk_b = (const float*)d_in[7];
    const float* rv_w = (const float*)d_in[8];
    const float* rv_s = (const float*)d_in[9];
    const float* rv_b = (const float*)d_in[10];
    const float* ik_w = (const float*)d_in[11];
    const float* ik_s = (const float*)d_in[12];
    const float* ik_b = (const float*)d_in[13];
    const float* iv_w = (const float*)d_in[14];
    const float* iv_s = (const float*)d_in[15];
    const float* iv_b = (const float*)d_in[16];
    const float* sr_w = (const float*)d_in[17];
    const float* sr_s = (const float*)d_in[18];
    const float* sr_b = (const float*)d_in[19];
    const float* g1   = (const float*)d_in[20];
    const float* g2   = (const float*)d_in[21];
    float* out = (float*)d_out;

    float *pQ, *prk, *prv, *pik, *piv, *prr, *pir;
    cudaGetSymbolAddress((void**)&pQ,  g_Q);
    cudaGetSymbolAddress((void**)&prk, g_rk);
    cudaGetSymbolAddress((void**)&prv, g_rv);
    cudaGetSymbolAddress((void**)&pik, g_ik);
    cudaGetSymbolAddress((void**)&piv, g_iv);
    cudaGetSymbolAddress((void**)&prr, g_rr);
    cudaGetSymbolAddress((void**)&pir, g_ir);

    cudaFuncSetAttribute(attn_k, cudaFuncAttributeMaxDynamicSharedMemorySize,
                         (int)ATT_SMEM);

    CPack pq = {};
    pq.c[0] = { x, y, q_w, q_s, q_b, pQ };
    conv_k<128><<<dim3(4, 4, 16), 256>>>(pq);

    CPack pk = {};
    pk.c[0] = { x, nullptr, rk_w, rk_s, rk_b, prk };
    pk.c[1] = { x, nullptr, rv_w, rv_s, rv_b, prv };
    pk.c[2] = { y, nullptr, ik_w, ik_s, ik_b, pik };
    pk.c[3] = { y, nullptr, iv_w, iv_s, iv_b, piv };
    conv_k<64><<<dim3(4, 4, 64), 256>>>(pk);

    attn_k<<<dim3(64, 4, 2), 128, ATT_SMEM>>>(x, y, g1, g2);

    CPack ps = {};
    ps.c[0] = { prr, pir, sr_w, sr_s, sr_b, out };
    conv_k<128><<<dim3(4, 4, 16), 256>>>(ps);
}

// round 7
// speedup vs baseline: 2.1713x; 1.8915x over previous
#include <cuda_runtime.h>
#include <cuda_bf16.h>
#include <cstdint>
#include <cstddef>

typedef unsigned long long ull;
typedef uint32_t u32;

#define BN 4
#define CH 64
#define NPIX 4096

// ---------- scratch ----------
__device__ float g_Q [BN*CH*NPIX];
__device__ float g_rk[BN*CH*NPIX];
__device__ float g_rv[BN*CH*NPIX];
__device__ float g_ik[BN*CH*NPIX];
__device__ float g_iv[BN*CH*NPIX];
__device__ float g_rr[BN*CH*NPIX];
__device__ float g_ir[BN*CH*NPIX];
// split-bf16 prepped operands (u32 = bf16x2), pitch 36 u32 (72 bf16)
__device__ u32 g_Khi[4*4096*36];
__device__ u32 g_Klo[4*4096*36];
__device__ u32 g_Vhi[8*4096*36];
__device__ u32 g_Vlo[8*4096*36];

// ---------- helpers ----------
__device__ __forceinline__ ull pk2(float a, float b) {
    ull r; asm("mov.b64 %0, {%1, %2};" : "=l"(r) : "f"(a), "f"(b)); return r;
}
__device__ __forceinline__ float2 up2(ull v) {
    float2 f; asm("mov.b64 {%0, %1}, %2;" : "=f"(f.x), "=f"(f.y) : "l"(v)); return f;
}
__device__ __forceinline__ void fma2(ull& d, ull a, ull b) {
    asm("fma.rn.f32x2 %0, %1, %2, %0;" : "+l"(d) : "l"(a), "l"(b));
}
__device__ __forceinline__ u32 s2u(const void* p) {
    u32 a; asm("{ .reg .u64 t; cvta.to.shared.u64 t, %1; cvt.u32.u64 %0, t; }" : "=r"(a) : "l"(p));
    return a;
}
__device__ __forceinline__ u32 cvt2bf(float hi, float lo) {   // {lo16=lo, hi16=hi}
    u32 r; asm("cvt.rn.bf16x2.f32 %0, %1, %2;" : "=r"(r) : "f"(hi), "f"(lo)); return r;
}
__device__ __forceinline__ float lo16f(u32 u) { return __uint_as_float(u << 16); }
__device__ __forceinline__ float hi16f(u32 u) { return __uint_as_float(u & 0xFFFF0000u); }

// ============================================================
// conv3x3+BN+ReLU: runtime cin, 16x16 tile, 8 oc/block,
// 4 in-chans per stage, cp.async double-buffered.
// grid z: conv = z>>5, b = (z>>3)&3, ocb = (z&7)*8
// ============================================================
struct CArg { const float* inA; const float* inB; const float* w;
              const float* s; const float* bb; float* out; int cin; };
struct CPack { CArg c[5]; };

__global__ void __launch_bounds__(256) conv_k(CPack P) {
    __shared__ float tile[2][4][360];   // 18 x 20
    __shared__ float wsm[2][4][80];     // 9 x 8
    const int tid = threadIdx.x;
    const int tx = tid & 15, ty = tid >> 4;
    const int z = blockIdx.z;
    const CArg a = P.c[z >> 5];
    const int b   = (z >> 3) & 3;
    const int ocb = (z & 7) << 3;
    const int ox0 = blockIdx.x << 4, oy0 = blockIdx.y << 4;
    const int ox = ox0 + tx, oy = oy0 + ty;
    const int S = a.cin >> 2;

    ull acc[4];
#pragma unroll
    for (int p = 0; p < 4; p++) acc[p] = 0ull;

    for (int st = 0; st <= S; st++) {
        if (st < S) {
            const int c0 = st * 4, sbf = st & 1;
            for (int i = tid; i < 1296; i += 256) {
                int pl = i / 324, r2 = i - pl * 324;
                int r = r2 / 18, c2 = r2 - r * 18;
                int ci = c0 + pl;
                const float* src = a.inA; int cc = ci;
                if (ci >= 64 && a.cin == 128) { src = a.inB; cc = ci - 64; }
                int iy = oy0 - 1 + r, ix = ox0 - 1 + c2;
                u32 ok = ((unsigned)iy < 64u && (unsigned)ix < 64u) ? 4u : 0u;
                const float* gp = src + ((size_t)b * 64 + cc) * 4096 +
                                  (ok ? iy * 64 + ix : 0);
                u32 sa = s2u(&tile[sbf][pl][r * 20 + c2]);
                asm volatile("cp.async.ca.shared.global [%0], [%1], 4, %2;"
                             :: "r"(sa), "l"(gp), "r"(ok));
            }
            for (int i = tid; i < 288; i += 256) {
                int pl = i / 72, j = i - pl * 72;
                int o = j & 7, k = j >> 3;
                const float* gp = a.w + ((size_t)(ocb + o) * a.cin + c0 + pl) * 9 + k;
                u32 sa = s2u(&wsm[sbf][pl][k * 8 + o]);
                asm volatile("cp.async.ca.shared.global [%0], [%1], 4;"
                             :: "r"(sa), "l"(gp));
            }
            asm volatile("cp.async.commit_group;" ::: "memory");
        }
        if (st == 0) continue;
        if (st < S) asm volatile("cp.async.wait_group 1;" ::: "memory");
        else        asm volatile("cp.async.wait_group 0;" ::: "memory");
        __syncthreads();
        const int sb = (st - 1) & 1;
#pragma unroll
        for (int pl = 0; pl < 4; pl++) {
            float v[9];
#pragma unroll
            for (int ky = 0; ky < 3; ky++)
#pragma unroll
                for (int kx = 0; kx < 3; kx++)
                    v[ky * 3 + kx] = tile[sb][pl][(ty + ky) * 20 + tx + kx];
#pragma unroll
            for (int k = 0; k < 9; k++) {
                ull vv = pk2(v[k], v[k]);
#pragma unroll
                for (int p = 0; p < 4; p++)
                    fma2(acc[p], vv, *(const ull*)(&wsm[sb][pl][k * 8 + 2 * p]));
            }
        }
        __syncthreads();
    }
#pragma unroll
    for (int p = 0; p < 4; p++) {
        float2 o2 = up2(acc[p]);
#pragma unroll
        for (int j = 0; j < 2; j++) {
            int oc = ocb + 2 * p + j;
            float val = fmaxf((j ? o2.y : o2.x) * a.s[oc] + a.bb[oc], 0.f);
            a.out[(((size_t)b * 64 + oc) * 64 + oy) * 64 + ox] = val;
        }
    }
}

// ============================================================
// prep: split-bf16 K [n][c] (from g_Q) and V [c][n] per chunk.
// grid (64 nt, 4 b, 3 sel): sel 0=K, 1=V(a0), 2=V(a1)
// ============================================================
__global__ void __launch_bounds__(256) prep_k() {
    __shared__ float st[64][65];
    const int tid = threadIdx.x;
    const int nt = blockIdx.x, b = blockIdx.y, sel = blockIdx.z;
    const float* src = (sel == 0 ? g_Q : (sel == 1 ? g_rv : g_iv));
    src += (size_t)b * CH * NPIX + nt * 64;
    for (int i = tid; i < 4096; i += 256) {
        int c = i >> 6, n = i & 63;
        st[c][n] = src[(size_t)c * NPIX + n];
    }
    __syncthreads();
    if (sel == 0) {
        u32* kh = g_Khi + ((size_t)b * 4096 + nt * 64) * 36;
        u32* kl = g_Klo + ((size_t)b * 4096 + nt * 64) * 36;
        for (int i = tid; i < 2048; i += 256) {
            int n = i >> 5, cp = i & 31;
            float f0 = st[2 * cp][n], f1 = st[2 * cp + 1][n];
            u32 h = cvt2bf(f1, f0);
            u32 l = cvt2bf(f1 - hi16f(h), f0 - lo16f(h));
            kh[n * 36 + cp] = h; kl[n * 36 + cp] = l;
        }
    } else {
        int av = sel - 1;
        u32* vh = g_Vhi + (((size_t)(av * 4 + b) * 64 + nt) * 64) * 36;
        u32* vl = g_Vlo + (((size_t)(av * 4 + b) * 64 + nt) * 64) * 36;
        for (int i = tid; i < 2048; i += 256) {
            int c = i >> 5, np = i & 31;
            float f0 = st[c][2 * np], f1 = st[c][2 * np + 1];
            u32 h = cvt2bf(f1, f0);
            u32 l = cvt2bf(f1 - hi16f(h), f0 - lo16f(h));
            vh[c * 36 + np] = h; vl[c * 36 + np] = l;
        }
    }
}

// ============================================================
// flash attention, warp mma, split-bf16 x3, cp.async double-buffered
// grid (64 mtiles, 4 b, 2 a), 128 threads
// ============================================================
#define MMA(d, a, b0_, b1_) \
    asm volatile("mma.sync.aligned.m16n8k16.row.col.f32.bf16.bf16.f32 " \
        "{%0,%1,%2,%3}, {%4,%5,%6,%7}, {%8,%9}, {%0,%1,%2,%3};" \
        : "+f"((d)[0]), "+f"((d)[1]), "+f"((d)[2]), "+f"((d)[3]) \
        : "r"((a)[0]), "r"((a)[1]), "r"((a)[2]), "r"((a)[3]), "r"(b0_), "r"(b1_))

#define PITCH 72
#define STG_BYTES 36864u     // KH 9216 | KL 9216 | VH 9216 | VL 9216
#define QS_OFF 73728u
#define ATT_SMEM 91136u

__device__ __forceinline__ void fetch_chunk(u32 sbase, int tid, int nt,
        const u32* kh, const u32* kl, const u32* vh, const u32* vl) {
    const u32 off = (u32)nt * 2304u;
#pragma unroll
    for (int k = 0; k < 18; k++) {
        int idx = tid + k * 128;          // 0..2303
        int r = idx / 576, l = idx - r * 576;
        const u32* gp = (r == 0 ? kh : r == 1 ? kl : r == 2 ? vh : vl) + off + l * 4;
        asm volatile("cp.async.cg.shared.global [%0], [%1], 16;"
                     :: "r"(sbase + r * 9216u + l * 16u), "l"(gp));
    }
    asm volatile("cp.async.commit_group;" ::: "memory");
}

__global__ void __launch_bounds__(128) attn_k(const float* __restrict__ x,
                                              const float* __restrict__ y,
                                              const float* __restrict__ g1,
                                              const float* __restrict__ g2) {
    extern __shared__ char smc[];
    float* Qs = (float*)(smc + QS_OFF);
    const u32 sbA = s2u(smc);
    const int tid = threadIdx.x;
    const int w = tid >> 5, lane = tid & 31;
    const int qr = lane >> 2, qc2 = (lane & 3) * 2;
    const int m0 = blockIdx.x * 64, b = blockIdx.y, a = blockIdx.z;

    const size_t boff = (size_t)b * CH * NPIX;
    const float* Aq  = (a ? g_ik : g_rk) + boff;
    const float* res = (a ? x : y) + boff;
    float* outp      = (a ? g_ir : g_rr) + boff;
    const float gamma = a ? g2[0] : g1[0];
    const u32* kh = g_Khi + (size_t)b * 147456;
    const u32* kl = g_Klo + (size_t)b * 147456;
    const u32* vh = g_Vhi + (size_t)(a * 4 + b) * 147456;
    const u32* vl = g_Vlo + (size_t)(a * 4 + b) * 147456;

    // stage Q tile [m][c] fp32; prefetch chunk 0 meanwhile
    fetch_chunk(sbA, tid, 0, kh, kl, vh, vl);
    for (int i = tid; i < 4096; i += 128) {
        int m = i & 63, c = i >> 6;
        Qs[m * 68 + c] = Aq[(size_t)c * NPIX + m0 + m];
    }
    __syncthreads();

    // Q fragments hi/lo
    u32 ah[4][4], al[4][4];
    const int r0 = w * 16 + qr;
#pragma unroll
    for (int j = 0; j < 4; j++) {
        int c0 = j * 16 + qc2;
        float2 fs[4] = { *(float2*)(Qs + r0 * 68 + c0),
                         *(float2*)(Qs + (r0 + 8) * 68 + c0),
                         *(float2*)(Qs + r0 * 68 + c0 + 8),
                         *(float2*)(Qs + (r0 + 8) * 68 + c0 + 8) };
#pragma unroll
        for (int r = 0; r < 4; r++) {
            u32 h = cvt2bf(fs[r].y, fs[r].x);
            ah[j][r] = h;
            al[j][r] = cvt2bf(fs[r].y - hi16f(h), fs[r].x - lo16f(h));
        }
    }

    float O[8][4];
#pragma unroll
    for (int f = 0; f < 8; f++)
#pragma unroll
        for (int r = 0; r < 4; r++) O[f][r] = 0.f;
    float M0 = -1e30f, M1 = -1e30f, L0 = 0.f, L1 = 0.f;

    for (int nt = 0; nt < 64; nt++) {
        if (nt < 63)
            fetch_chunk(sbA + ((nt + 1) & 1) * STG_BYTES, tid, nt + 1, kh, kl, vh, vl);
        if (nt < 63) asm volatile("cp.async.wait_group 1;" ::: "memory");
        else         asm volatile("cp.async.wait_group 0;" ::: "memory");
        __syncthreads();
        const char* sbuf = smc + (nt & 1) * STG_BYTES;

        // ---- S = Q K^T, 3-term split ----
        float S[8][4];
#pragma unroll
        for (int f = 0; f < 8; f++)
#pragma unroll
            for (int r = 0; r < 4; r++) S[f][r] = 0.f;
#pragma unroll
        for (int f = 0; f < 8; f++) {
            const char* kb = sbuf + ((f * 8 + qr) * PITCH + qc2) * 2;
#pragma unroll
            for (int j = 0; j < 4; j++) {
                u32 kh0 = *(const u32*)(kb + j * 32);
                u32 kh1 = *(const u32*)(kb + j * 32 + 16);
                u32 kl0 = *(const u32*)(kb + 9216 + j * 32);
                u32 kl1 = *(const u32*)(kb + 9216 + j * 32 + 16);
                MMA(S[f], ah[j], kh0, kh1);
                MMA(S[f], al[j], kh0, kh1);
                MMA(S[f], ah[j], kl0, kl1);
            }
        }

        // ---- online softmax ----
        float mx0 = -1e30f, mx1 = -1e30f;
#pragma unroll
        for (int f = 0; f < 8; f++) {
            mx0 = fmaxf(mx0, fmaxf(S[f][0], S[f][1]));
            mx1 = fmaxf(mx1, fmaxf(S[f][2], S[f][3]));
        }
        mx0 = fmaxf(mx0, __shfl_xor_sync(0xffffffffu, mx0, 1));
        mx0 = fmaxf(mx0, __shfl_xor_sync(0xffffffffu, mx0, 2));
        mx1 = fmaxf(mx1, __shfl_xor_sync(0xffffffffu, mx1, 1));
        mx1 = fmaxf(mx1, __shfl_xor_sync(0xffffffffu, mx1, 2));
        float mn0 = fmaxf(M0, mx0), mn1 = fmaxf(M1, mx1);
        float sc0 = __expf(M0 - mn0), sc1 = __expf(M1 - mn1);
        M0 = mn0; M1 = mn1;
        float s0 = 0.f, s1 = 0.f;
#pragma unroll
        for (int f = 0; f < 8; f++) {
            S[f][0] = __expf(S[f][0] - M0); S[f][1] = __expf(S[f][1] - M0);
            S[f][2] = __expf(S[f][2] - M1); S[f][3] = __expf(S[f][3] - M1);
            s0 += S[f][0] + S[f][1];
            s1 += S[f][2] + S[f][3];
        }
        s0 += __shfl_xor_sync(0xffffffffu, s0, 1);
        s0 += __shfl_xor_sync(0xffffffffu, s0, 2);
        s1 += __shfl_xor_sync(0xffffffffu, s1, 1);
        s1 += __shfl_xor_sync(0xffffffffu, s1, 2);
        L0 = L0 * sc0 + s0;
        L1 = L1 * sc1 + s1;
#pragma unroll
        for (int f = 0; f < 8; f++) {
            O[f][0] *= sc0; O[f][1] *= sc0;
            O[f][2] *= sc1; O[f][3] *= sc1;
        }

        // ---- O += P V^T ----
#pragma unroll
        for (int j2 = 0; j2 < 4; j2++) {
            u32 ph[4], pl2[4];
#pragma unroll
            for (int h2 = 0; h2 < 2; h2++) {
                float p0a = S[2*j2][2*h2],   p1a = S[2*j2][2*h2+1];
                float p0b = S[2*j2+1][2*h2], p1b = S[2*j2+1][2*h2+1];
                u32 hA = cvt2bf(p1a, p0a);
                u32 hB = cvt2bf(p1b, p0b);
                ph[h2]      = hA;
                ph[h2 + 2]  = hB;
                pl2[h2]     = cvt2bf(p1a - hi16f(hA), p0a - lo16f(hA));
                pl2[h2 + 2] = cvt2bf(p1b - hi16f(hB), p0b - lo16f(hB));
            }
            const char* vb = sbuf + 18432 + (qr * PITCH + j2 * 16 + qc2) * 2;
#pragma unroll
            for (int fc = 0; fc < 8; fc++) {
                u32 vh0 = *(const u32*)(vb + fc * 8 * PITCH * 2);
                u32 vh1 = *(const u32*)(vb + fc * 8 * PITCH * 2 + 16);
                u32 vl0 = *(const u32*)(vb + 9216 + fc * 8 * PITCH * 2);
                u32 vl1 = *(const u32*)(vb + 9216 + fc * 8 * PITCH * 2 + 16);
                MMA(O[fc], ph, vh0, vh1);
                MMA(O[fc], pl2, vh0, vh1);
                MMA(O[fc], ph, vl0, vl1);
            }
        }
        __syncthreads();
    }

    // ---- epilogue ----
    float i0 = 1.0f / L0, i1 = 1.0f / L1;
    const int mA = m0 + r0, mB = mA + 8;
#pragma unroll
    for (int fc = 0; fc < 8; fc++) {
        int c0 = fc * 8 + qc2;
        size_t iA0 = (size_t)c0 * NPIX + mA;
        size_t iA1 = (size_t)(c0 + 1) * NPIX + mA;
        outp[iA0] = gamma * (O[fc][0] * i0) + res[iA0];
        outp[iA1] = gamma * (O[fc][1] * i0) + res[iA1];
        size_t iB0 = (size_t)c0 * NPIX + mB;
        size_t iB1 = (size_t)(c0 + 1) * NPIX + mB;
        outp[iB0] = gamma * (O[fc][2] * i1) + res[iB0];
        outp[iB1] = gamma * (O[fc][3] * i1) + res[iB1];
    }
}

// ============================================================
extern "C" void kernel_launch(void* const* d_in, const int* in_sizes, int n_in,
                              void* d_out, int out_size) {
    const float* x    = (const float*)d_in[0];
    const float* y    = (const float*)d_in[1];
    const float* q_w  = (const float*)d_in[2];
    const float* q_s  = (const float*)d_in[3];
    const float* q_b  = (const float*)d_in[4];
    const float* rk_w = (const float*)d_in[5];
    const float* rk_s = (const float*)d_in[6];
    const float* rk_b = (const float*)d_in[7];
    const float* rv_w = (const float*)d_in[8];
    const float* rv_s = (const float*)d_in[9];
    const float* rv_b = (const float*)d_in[10];
    const float* ik_w = (const float*)d_in[11];
    const float* ik_s = (const float*)d_in[12];
    const float* ik_b = (const float*)d_in[13];
    const float* iv_w = (const float*)d_in[14];
    const float* iv_s = (const float*)d_in[15];
    const float* iv_b = (const float*)d_in[16];
    const float* sr_w = (const float*)d_in[17];
    const float* sr_s = (const float*)d_in[18];
    const float* sr_b = (const float*)d_in[19];
    const float* g1   = (const float*)d_in[20];
    const float* g2   = (const float*)d_in[21];
    float* out = (float*)d_out;

    float *pQ, *prk, *prv, *pik, *piv, *prr, *pir;
    cudaGetSymbolAddress((void**)&pQ,  g_Q);
    cudaGetSymbolAddress((void**)&prk, g_rk);
    cudaGetSymbolAddress((void**)&prv, g_rv);
    cudaGetSymbolAddress((void**)&pik, g_ik);
    cudaGetSymbolAddress((void**)&piv, g_iv);
    cudaGetSymbolAddress((void**)&prr, g_rr);
    cudaGetSymbolAddress((void**)&pir, g_ir);

    cudaFuncSetAttribute(attn_k, cudaFuncAttributeMaxDynamicSharedMemorySize,
                         (int)ATT_SMEM);

    // producers: Q conv (cin 128) + 4 K/V convs (cin 64) in one launch
    CPack pp = {};
    pp.c[0] = { x, y,       q_w,  q_s,  q_b,  pQ,  128 };
    pp.c[1] = { x, nullptr, rk_w, rk_s, rk_b, prk, 64 };
    pp.c[2] = { x, nullptr, rv_w, rv_s, rv_b, prv, 64 };
    pp.c[3] = { y, nullptr, ik_w, ik_s, ik_b, pik, 64 };
    pp.c[4] = { y, nullptr, iv_w, iv_s, iv_b, piv, 64 };
    conv_k<<<dim3(4, 4, 160), 256>>>(pp);

    prep_k<<<dim3(64, 4, 3), 256>>>();

    attn_k<<<dim3(64, 4, 2), 128, ATT_SMEM>>>(x, y, g1, g2);

    CPack ps = {};
    ps.c[0] = { prr, pir, sr_w, sr_s, sr_b, out, 128 };
    conv_k<<<dim3(4, 4, 32), 256>>>(ps);
}

// round 8
// speedup vs baseline: 2.3526x; 1.0835x over previous
#include <cuda_runtime.h>
#include <cuda_bf16.h>
#include <cstdint>
#include <cstddef>

typedef unsigned long long ull;
typedef uint32_t u32;

#define BN 4
#define CH 64
#define NPIX 4096

// ---------- scratch ----------
__device__ float g_rk[BN*CH*NPIX];
__device__ float g_ik[BN*CH*NPIX];
__device__ float g_rr[BN*CH*NPIX];
__device__ float g_ir[BN*CH*NPIX];
// split-bf16 operands (u32 = bf16x2), pitch 36 u32 (72 bf16)
__device__ u32 g_Khi[4*4096*36];
__device__ u32 g_Klo[4*4096*36];
__device__ u32 g_Vhi[8*4096*36];
__device__ u32 g_Vlo[8*4096*36];

// ---------- helpers ----------
__device__ __forceinline__ ull pk2(float a, float b) {
    ull r; asm("mov.b64 %0, {%1, %2};" : "=l"(r) : "f"(a), "f"(b)); return r;
}
__device__ __forceinline__ float2 up2(ull v) {
    float2 f; asm("mov.b64 {%0, %1}, %2;" : "=f"(f.x), "=f"(f.y) : "l"(v)); return f;
}
__device__ __forceinline__ void fma2(ull& d, ull a, ull b) {
    asm("fma.rn.f32x2 %0, %1, %2, %0;" : "+l"(d) : "l"(a), "l"(b));
}
__device__ __forceinline__ u32 s2u(const void* p) {
    u32 a; asm("{ .reg .u64 t; cvta.to.shared.u64 t, %1; cvt.u32.u64 %0, t; }" : "=r"(a) : "l"(p));
    return a;
}
__device__ __forceinline__ u32 cvt2bf(float hi, float lo) {   // {lo16=lo, hi16=hi}
    u32 r; asm("cvt.rn.bf16x2.f32 %0, %1, %2;" : "=r"(r) : "f"(hi), "f"(lo)); return r;
}
__device__ __forceinline__ float lo16f(u32 u) { return __uint_as_float(u << 16); }
__device__ __forceinline__ float hi16f(u32 u) { return __uint_as_float(u & 0xFFFF0000u); }

// ============================================================
// conv3x3+BN+ReLU: runtime cin, 16x16 tile, 8 oc/block,
// 4 in-chans per stage, cp.async double-buffered.
// mode 0: fp32 out. mode 1: split-bf16 K [n][cp]. mode 2: V [c][np].
// ============================================================
struct CArg { const float* inA; const float* inB; const float* w;
              const float* s; const float* bb; float* out; int cin; int mode; int av; };
struct CPack { CArg c[5]; };

__global__ void __launch_bounds__(256) conv_k(CPack P) {
    __shared__ float tile[2][4][360];   // 18 x 20
    __shared__ float wsm[2][4][80];     // 9 x 8
    const int tid = threadIdx.x;
    const int tx = tid & 15, ty = tid >> 4;
    const int z = blockIdx.z;
    const CArg a = P.c[z >> 5];
    const int b   = (z >> 3) & 3;
    const int ocb = (z & 7) << 3;
    const int ox0 = blockIdx.x << 4, oy0 = blockIdx.y << 4;
    const int ox = ox0 + tx, oy = oy0 + ty;
    const int S = a.cin >> 2;

    ull acc[4];
#pragma unroll
    for (int p = 0; p < 4; p++) acc[p] = 0ull;

    for (int st = 0; st <= S; st++) {
        if (st < S) {
            const int c0 = st * 4, sbf = st & 1;
            for (int i = tid; i < 1296; i += 256) {
                int pl = i / 324, r2 = i - pl * 324;
                int r = r2 / 18, c2 = r2 - r * 18;
                int ci = c0 + pl;
                const float* src = a.inA; int cc = ci;
                if (ci >= 64 && a.cin == 128) { src = a.inB; cc = ci - 64; }
                int iy = oy0 - 1 + r, ix = ox0 - 1 + c2;
                u32 ok = ((unsigned)iy < 64u && (unsigned)ix < 64u) ? 4u : 0u;
                const float* gp = src + ((size_t)b * 64 + cc) * 4096 +
                                  (ok ? iy * 64 + ix : 0);
                u32 sa = s2u(&tile[sbf][pl][r * 20 + c2]);
                asm volatile("cp.async.ca.shared.global [%0], [%1], 4, %2;"
                             :: "r"(sa), "l"(gp), "r"(ok));
            }
            for (int i = tid; i < 288; i += 256) {
                int pl = i / 72, j = i - pl * 72;
                int o = j & 7, k = j >> 3;
                const float* gp = a.w + ((size_t)(ocb + o) * a.cin + c0 + pl) * 9 + k;
                u32 sa = s2u(&wsm[sbf][pl][k * 8 + o]);
                asm volatile("cp.async.ca.shared.global [%0], [%1], 4;"
                             :: "r"(sa), "l"(gp));
            }
            asm volatile("cp.async.commit_group;" ::: "memory");
        }
        if (st == 0) continue;
        if (st < S) asm volatile("cp.async.wait_group 1;" ::: "memory");
        else        asm volatile("cp.async.wait_group 0;" ::: "memory");
        __syncthreads();
        const int sb = (st - 1) & 1;
#pragma unroll
        for (int pl = 0; pl < 4; pl++) {
            float v[9];
#pragma unroll
            for (int ky = 0; ky < 3; ky++)
#pragma unroll
                for (int kx = 0; kx < 3; kx++)
                    v[ky * 3 + kx] = tile[sb][pl][(ty + ky) * 20 + tx + kx];
#pragma unroll
            for (int k = 0; k < 9; k++) {
                ull vv = pk2(v[k], v[k]);
#pragma unroll
                for (int p = 0; p < 4; p++)
                    fma2(acc[p], vv, *(const ull*)(&wsm[sb][pl][k * 8 + 2 * p]));
            }
        }
        __syncthreads();
    }

    float vals[8];
#pragma unroll
    for (int p = 0; p < 4; p++) {
        float2 o2 = up2(acc[p]);
        vals[2*p]   = fmaxf(o2.x * a.s[ocb + 2*p]     + a.bb[ocb + 2*p],     0.f);
        vals[2*p+1] = fmaxf(o2.y * a.s[ocb + 2*p + 1] + a.bb[ocb + 2*p + 1], 0.f);
    }
    if (a.mode == 0) {
#pragma unroll
        for (int j = 0; j < 8; j++)
            a.out[(((size_t)b * 64 + ocb + j) * 64 + oy) * 64 + ox] = vals[j];
    } else if (a.mode == 1) {
        // K: [b][n][cp], pair over c
        const size_t nbase = ((size_t)b * 4096 + oy * 64 + ox) * 36 + (ocb >> 1);
#pragma unroll
        for (int p = 0; p < 4; p++) {
            u32 h = cvt2bf(vals[2*p+1], vals[2*p]);
            u32 l = cvt2bf(vals[2*p+1] - hi16f(h), vals[2*p] - lo16f(h));
            g_Khi[nbase + p] = h;
            g_Klo[nbase + p] = l;
        }
    } else {
        // V: [av*4+b][oy(=nt)][c][np], pair over n (adjacent lanes)
        const int lane = tid & 31;
        const int np = ox >> 1;
#pragma unroll
        for (int j = 0; j < 8; j++) {
            float v = vals[j];
            float vp = __shfl_xor_sync(0xffffffffu, v, 1);
            if (!(lane & 1)) {
                u32 h = cvt2bf(vp, v);
                u32 l = cvt2bf(vp - hi16f(h), v - lo16f(h));
                size_t idx = (((size_t)(a.av * 4 + b) * 64 + oy) * 64 + ocb + j) * 36 + np;
                g_Vhi[idx] = h;
                g_Vlo[idx] = l;
            }
        }
    }
}

// ============================================================
// flash attention: warp mma split-bf16 x3, m-tile 128, 256 thr,
// fixed-shift softmax (chunk-0 row max), double-buffered cp.async
// grid (32 mtiles, 4 b, 2 a)
// ============================================================
#define MMA(d, a, b0_, b1_) \
    asm volatile("mma.sync.aligned.m16n8k16.row.col.f32.bf16.bf16.f32 " \
        "{%0,%1,%2,%3}, {%4,%5,%6,%7}, {%8,%9}, {%0,%1,%2,%3};" \
        : "+f"((d)[0]), "+f"((d)[1]), "+f"((d)[2]), "+f"((d)[3]) \
        : "r"((a)[0]), "r"((a)[1]), "r"((a)[2]), "r"((a)[3]), "r"(b0_), "r"(b1_))

#define PITCH 72
#define STG_BYTES 36864u     // KH 9216 | KL 9216 | VH 9216 | VL 9216
#define QS_OFF 36864u        // Q stage overlays buffer 1
#define ATT_SMEM 73728u

__device__ __forceinline__ void fetch_chunk(u32 sbase, int tid, int nt,
        const u32* kh, const u32* kl, const u32* vh, const u32* vl) {
    const u32 off = (u32)nt * 2304u;
#pragma unroll
    for (int k = 0; k < 9; k++) {
        int idx = tid + k * 256;          // 0..2303
        int r = idx / 576, l = idx - r * 576;
        const u32* gp = (r == 0 ? kh : r == 1 ? kl : r == 2 ? vh : vl) + off + l * 4;
        asm volatile("cp.async.cg.shared.global [%0], [%1], 16;"
                     :: "r"(sbase + r * 9216u + l * 16u), "l"(gp));
    }
    asm volatile("cp.async.commit_group;" ::: "memory");
}

__global__ void __launch_bounds__(256) attn_k(const float* __restrict__ x,
                                              const float* __restrict__ y,
                                              const float* __restrict__ g1,
                                              const float* __restrict__ g2) {
    extern __shared__ char smc[];
    float* Qs = (float*)(smc + QS_OFF);
    const u32 sbA = s2u(smc);
    const int tid = threadIdx.x;
    const int w = tid >> 5, lane = tid & 31;
    const int qr = lane >> 2, qc2 = (lane & 3) * 2;
    const int m0 = blockIdx.x * 128, b = blockIdx.y, a = blockIdx.z;

    const size_t boff = (size_t)b * CH * NPIX;
    const float* Aq  = (a ? g_ik : g_rk) + boff;
    const float* res = (a ? x : y) + boff;
    float* outp      = (a ? g_ir : g_rr) + boff;
    const float gamma = a ? g2[0] : g1[0];
    const u32* kh = g_Khi + (size_t)b * 147456;
    const u32* kl = g_Klo + (size_t)b * 147456;
    const u32* vh = g_Vhi + (size_t)(a * 4 + b) * 147456;
    const u32* vl = g_Vlo + (size_t)(a * 4 + b) * 147456;

    // prefetch chunk 0 into buf0; stage Q [m][c] fp32 into buf1 region
    fetch_chunk(sbA, tid, 0, kh, kl, vh, vl);
    for (int i = tid; i < 8192; i += 256) {
        int m = i & 127, c = i >> 7;
        Qs[m * 68 + c] = Aq[(size_t)c * NPIX + m0 + m];
    }
    __syncthreads();

    // Q fragments hi/lo (row-major A)
    u32 ah[4][4], al[4][4];
    const int r0 = w * 16 + qr;
#pragma unroll
    for (int j = 0; j < 4; j++) {
        int c0 = j * 16 + qc2;
        float2 fs[4] = { *(float2*)(Qs + r0 * 68 + c0),
                         *(float2*)(Qs + (r0 + 8) * 68 + c0),
                         *(float2*)(Qs + r0 * 68 + c0 + 8),
                         *(float2*)(Qs + (r0 + 8) * 68 + c0 + 8) };
#pragma unroll
        for (int r = 0; r < 4; r++) {
            u32 h = cvt2bf(fs[r].y, fs[r].x);
            ah[j][r] = h;
            al[j][r] = cvt2bf(fs[r].y - hi16f(h), fs[r].x - lo16f(h));
        }
    }
    __syncthreads();   // Q reads done before chunk-1 prefetch overwrites Qs

    float O[8][4];
#pragma unroll
    for (int f = 0; f < 8; f++)
#pragma unroll
        for (int r = 0; r < 4; r++) O[f][r] = 0.f;
    float M0 = 0.f, M1 = 0.f, L0 = 0.f, L1 = 0.f;

    for (int nt = 0; nt < 64; nt++) {
        if (nt < 63)
            fetch_chunk(sbA + ((nt + 1) & 1) * STG_BYTES, tid, nt + 1, kh, kl, vh, vl);
        if (nt < 63) asm volatile("cp.async.wait_group 1;" ::: "memory");
        else         asm volatile("cp.async.wait_group 0;" ::: "memory");
        __syncthreads();
        const char* sbuf = smc + (nt & 1) * STG_BYTES;

        // ---- S = Q K^T, 3-term split ----
        float S[8][4];
#pragma unroll
        for (int f = 0; f < 8; f++)
#pragma unroll
            for (int r = 0; r < 4; r++) S[f][r] = 0.f;
#pragma unroll
        for (int f = 0; f < 8; f++) {
            const char* kb = sbuf + ((f * 8 + qr) * PITCH + qc2) * 2;
#pragma unroll
            for (int j = 0; j < 4; j++) {
                u32 kh0 = *(const u32*)(kb + j * 32);
                u32 kh1 = *(const u32*)(kb + j * 32 + 16);
                u32 kl0 = *(const u32*)(kb + 9216 + j * 32);
                u32 kl1 = *(const u32*)(kb + 9216 + j * 32 + 16);
                MMA(S[f], ah[j], kh0, kh1);
                MMA(S[f], al[j], kh0, kh1);
                MMA(S[f], ah[j], kl0, kl1);
            }
        }

        // ---- fixed-shift softmax: chunk 0 sets the row shift ----
        if (nt == 0) {
            float mx0 = -1e30f, mx1 = -1e30f;
#pragma unroll
            for (int f = 0; f < 8; f++) {
                mx0 = fmaxf(mx0, fmaxf(S[f][0], S[f][1]));
                mx1 = fmaxf(mx1, fmaxf(S[f][2], S[f][3]));
            }
            mx0 = fmaxf(mx0, __shfl_xor_sync(0xffffffffu, mx0, 1));
            mx0 = fmaxf(mx0, __shfl_xor_sync(0xffffffffu, mx0, 2));
            mx1 = fmaxf(mx1, __shfl_xor_sync(0xffffffffu, mx1, 1));
            mx1 = fmaxf(mx1, __shfl_xor_sync(0xffffffffu, mx1, 2));
            M0 = mx0; M1 = mx1;
        }
#pragma unroll
        for (int f = 0; f < 8; f++) {
            S[f][0] = __expf(S[f][0] - M0); S[f][1] = __expf(S[f][1] - M0);
            S[f][2] = __expf(S[f][2] - M1); S[f][3] = __expf(S[f][3] - M1);
            L0 += S[f][0] + S[f][1];
            L1 += S[f][2] + S[f][3];
        }

        // ---- O += P V^T ----
#pragma unroll
        for (int j2 = 0; j2 < 4; j2++) {
            u32 ph[4], pl2[4];
#pragma unroll
            for (int h2 = 0; h2 < 2; h2++) {
                float p0a = S[2*j2][2*h2],   p1a = S[2*j2][2*h2+1];
                float p0b = S[2*j2+1][2*h2], p1b = S[2*j2+1][2*h2+1];
                u32 hA = cvt2bf(p1a, p0a);
                u32 hB = cvt2bf(p1b, p0b);
                ph[h2]      = hA;
                ph[h2 + 2]  = hB;
                pl2[h2]     = cvt2bf(p1a - hi16f(hA), p0a - lo16f(hA));
                pl2[h2 + 2] = cvt2bf(p1b - hi16f(hB), p0b - lo16f(hB));
            }
            const char* vb = sbuf + 18432 + (qr * PITCH + j2 * 16 + qc2) * 2;
#pragma unroll
            for (int fc = 0; fc < 8; fc++) {
                u32 vh0 = *(const u32*)(vb + fc * 8 * PITCH * 2);
                u32 vh1 = *(const u32*)(vb + fc * 8 * PITCH * 2 + 16);
                u32 vl0 = *(const u32*)(vb + 9216 + fc * 8 * PITCH * 2);
                u32 vl1 = *(const u32*)(vb + 9216 + fc * 8 * PITCH * 2 + 16);
                MMA(O[fc], ph, vh0, vh1);
                MMA(O[fc], pl2, vh0, vh1);
                MMA(O[fc], ph, vl0, vl1);
            }
        }
        __syncthreads();
    }

    // ---- final L reduction (quad) + epilogue ----
    L0 += __shfl_xor_sync(0xffffffffu, L0, 1);
    L0 += __shfl_xor_sync(0xffffffffu, L0, 2);
    L1 += __shfl_xor_sync(0xffffffffu, L1, 1);
    L1 += __shfl_xor_sync(0xffffffffu, L1, 2);
    float i0 = 1.0f / L0, i1 = 1.0f / L1;
    const int mA = m0 + r0, mB = mA + 8;
#pragma unroll
    for (int fc = 0; fc < 8; fc++) {
        int c0 = fc * 8 + qc2;
        size_t iA0 = (size_t)c0 * NPIX + mA;
        size_t iA1 = (size_t)(c0 + 1) * NPIX + mA;
        outp[iA0] = gamma * (O[fc][0] * i0) + res[iA0];
        outp[iA1] = gamma * (O[fc][1] * i0) + res[iA1];
        size_t iB0 = (size_t)c0 * NPIX + mB;
        size_t iB1 = (size_t)(c0 + 1) * NPIX + mB;
        outp[iB0] = gamma * (O[fc][2] * i1) + res[iB0];
        outp[iB1] = gamma * (O[fc][3] * i1) + res[iB1];
    }
}

// ============================================================
extern "C" void kernel_launch(void* const* d_in, const int* in_sizes, int n_in,
                              void* d_out, int out_size) {
    const float* x    = (const float*)d_in[0];
    const float* y    = (const float*)d_in[1];
    const float* q_w  = (const float*)d_in[2];
    const float* q_s  = (const float*)d_in[3];
    const float* q_b  = (const float*)d_in[4];
    const float* rk_w = (const float*)d_in[5];
    const float* rk_s = (const float*)d_in[6];
    const float* rk_b = (const float*)d_in[7];
    const float* rv_w = (const float*)d_in[8];
    const float* rv_s = (const float*)d_in[9];
    const float* rv_b = (const float*)d_in[10];
    const float* ik_w = (const float*)d_in[11];
    const float* ik_s = (const float*)d_in[12];
    const float* ik_b = (const float*)d_in[13];
    const float* iv_w = (const float*)d_in[14];
    const float* iv_s = (const float*)d_in[15];
    const float* iv_b = (const float*)d_in[16];
    const float* sr_w = (const float*)d_in[17];
    const float* sr_s = (const float*)d_in[18];
    const float* sr_b = (const float*)d_in[19];
    const float* g1   = (const float*)d_in[20];
    const float* g2   = (const float*)d_in[21];
    float* out = (float*)d_out;

    float *prk, *pik, *prr, *pir;
    cudaGetSymbolAddress((void**)&prk, g_rk);
    cudaGetSymbolAddress((void**)&pik, g_ik);
    cudaGetSymbolAddress((void**)&prr, g_rr);
    cudaGetSymbolAddress((void**)&pir, g_ir);

    cudaFuncSetAttribute(attn_k, cudaFuncAttributeMaxDynamicSharedMemorySize,
                         (int)ATT_SMEM);

    // producers: Q conv -> K split (mode 1), rk/ik -> fp32 (mode 0),
    // rv/iv -> V split (mode 2)
    CPack pp = {};
    pp.c[0] = { x, y,       q_w,  q_s,  q_b,  nullptr, 128, 1, 0 };
    pp.c[1] = { x, nullptr, rk_w, rk_s, rk_b, prk,      64, 0, 0 };
    pp.c[2] = { x, nullptr, rv_w, rv_s, rv_b, nullptr,  64, 2, 0 };
    pp.c[3] = { y, nullptr, ik_w, ik_s, ik_b, pik,      64, 0, 0 };
    pp.c[4] = { y, nullptr, iv_w, iv_s, iv_b, nullptr,  64, 2, 1 };
    conv_k<<<dim3(4, 4, 160), 256>>>(pp);

    attn_k<<<dim3(32, 4, 2), 256, ATT_SMEM>>>(x, y, g1, g2);

    CPack ps = {};
    ps.c[0] = { prr, pir, sr_w, sr_s, sr_b, out, 128, 0, 0 };
    conv_k<<<dim3(4, 4, 32), 256>>>(ps);
}

// round 9
// speedup vs baseline: 2.5926x; 1.1020x over previous
#include <cuda_runtime.h>
#include <cuda_bf16.h>
#include <cstdint>
#include <cstddef>

typedef unsigned long long ull;
typedef uint32_t u32;

#define BN 4
#define CH 64
#define NPIX 4096

// ---------- scratch ----------
__device__ float g_rk[BN*CH*NPIX];
__device__ float g_ik[BN*CH*NPIX];
__device__ float g_rr[BN*CH*NPIX];
__device__ float g_ir[BN*CH*NPIX];
// split-bf16 operands (u32 = bf16x2), pitch 36 u32 (72 bf16)
__device__ u32 g_Khi[4*4096*36];
__device__ u32 g_Klo[4*4096*36];
__device__ u32 g_Vhi[8*4096*36];
__device__ u32 g_Vlo[8*4096*36];

// ---------- helpers ----------
__device__ __forceinline__ ull pk2(float a, float b) {
    ull r; asm("mov.b64 %0, {%1, %2};" : "=l"(r) : "f"(a), "f"(b)); return r;
}
__device__ __forceinline__ float2 up2(ull v) {
    float2 f; asm("mov.b64 {%0, %1}, %2;" : "=f"(f.x), "=f"(f.y) : "l"(v)); return f;
}
__device__ __forceinline__ void fma2(ull& d, ull a, ull b) {
    asm("fma.rn.f32x2 %0, %1, %2, %0;" : "+l"(d) : "l"(a), "l"(b));
}
__device__ __forceinline__ u32 s2u(const void* p) {
    u32 a; asm("{ .reg .u64 t; cvta.to.shared.u64 t, %1; cvt.u32.u64 %0, t; }" : "=r"(a) : "l"(p));
    return a;
}
__device__ __forceinline__ u32 cvt2bf(float hi, float lo) {   // {lo16=lo, hi16=hi}
    u32 r; asm("cvt.rn.bf16x2.f32 %0, %1, %2;" : "=r"(r) : "f"(hi), "f"(lo)); return r;
}
__device__ __forceinline__ float lo16f(u32 u) { return __uint_as_float(u << 16); }
__device__ __forceinline__ float hi16f(u32 u) { return __uint_as_float(u & 0xFFFF0000u); }

// ============================================================
// conv3x3+BN+ReLU: runtime cin, 16x16 tile, OCB oc/block,
// 4 in-chans/stage, cp.async double-buffered, hoisted indexing.
// mode 0: fp32 out. mode 1: split-bf16 K [n][cp]. mode 2: V [c][np].
// ============================================================
struct CArg { const float* inA; const float* inB; const float* w;
              const float* s; const float* bb; float* out; int cin; int mode; int av; };
struct CPack { CArg c[5]; };

template<int OCB>
__global__ void __launch_bounds__(256) conv_k(CPack P) {
    constexpr int GR = 64 / OCB;            // ocb groups per (conv,b)
    constexpr int NWELEM = 36 * OCB;        // weight floats per stage
    constexpr int NW = (NWELEM + 255) / 256;
    __shared__ float tile[2][4][360];       // 18 x 20 per plane
    __shared__ float wsm[2][4][9 * OCB];
    const int tid = threadIdx.x;
    const int tx = tid & 15, ty = tid >> 4;
    const int z = blockIdx.z;
    const CArg a = P.c[z / (4 * GR)];
    const int b   = (z / GR) & 3;
    const int ocb = (z % GR) * OCB;
    const int ox0 = blockIdx.x << 4, oy0 = blockIdx.y << 4;
    const int ox = ox0 + tx, oy = oy0 + ty;
    const int S = a.cin >> 2;
    const bool wide = (a.cin == 128);

    const float* baseA = a.inA + (size_t)b * 64 * 4096;
    const float* baseB = wide ? a.inB + (size_t)b * 64 * 4096 : baseA;

    // ---- hoist tile-load slots (stage-invariant) ----
    u32 t_sa[6], t_go[6], t_ok[6]; int t_pl[6];
#pragma unroll
    for (int s = 0; s < 6; s++) {
        int i = tid + s * 256;
        if (i >= 1296) i = 0;               // clamp (slot 5 issued only if tid<16)
        int pl = i / 324, r2 = i - pl * 324;
        int r = r2 / 18, c2 = r2 - r * 18;
        int iy = oy0 - 1 + r, ix = ox0 - 1 + c2;
        bool ib = (unsigned)iy < 64u && (unsigned)ix < 64u;
        t_pl[s] = pl;
        t_ok[s] = ib ? 4u : 0u;
        t_go[s] = ib ? (u32)(iy * 64 + ix) : 0u;
        t_sa[s] = s2u(&tile[0][pl][r * 20 + c2]);
    }
    // ---- hoist weight-load slots ----
    u32 w_go[NW], w_sa[NW];
#pragma unroll
    for (int s = 0; s < NW; s++) {
        int j = tid + s * 256;
        if (j >= NWELEM) j = 0;
        int pl = j / (9 * OCB), rem = j - pl * (9 * OCB);
        int k = rem / OCB, o = rem - k * OCB;
        w_go[s] = (u32)(((ocb + o) * a.cin + pl) * 9 + k);
        w_sa[s] = s2u(&wsm[0][pl][k * OCB + o]);
    }

    ull acc[OCB / 2];
#pragma unroll
    for (int p = 0; p < OCB / 2; p++) acc[p] = 0ull;

    for (int st = 0; st <= S; st++) {
        if (st < S) {
            const int c0 = st * 4;
            const u32 tadd = (st & 1) ? 5760u : 0u;
            const u32 wadd = (st & 1) ? (u32)(144 * OCB) : 0u;
#pragma unroll
            for (int s = 0; s < 6; s++) {
                if (s == 5 && tid >= 16) break;
                int ci = c0 + t_pl[s];
                const float* gp = ((wide && ci >= 64) ? baseB : baseA)
                                  + (ci & 63) * 4096 + t_go[s];
                asm volatile("cp.async.ca.shared.global [%0], [%1], 4, %2;"
                             :: "r"(t_sa[s] + tadd), "l"(gp), "r"(t_ok[s]));
            }
#pragma unroll
            for (int s = 0; s < NW; s++) {
                if (s == NW - 1 && tid >= NWELEM - (NW - 1) * 256) break;
                const float* gp = a.w + w_go[s] + c0 * 9;
                asm volatile("cp.async.ca.shared.global [%0], [%1], 4;"
                             :: "r"(w_sa[s] + wadd), "l"(gp));
            }
            asm volatile("cp.async.commit_group;" ::: "memory");
        }
        if (st == 0) continue;
        if (st < S) asm volatile("cp.async.wait_group 1;" ::: "memory");
        else        asm volatile("cp.async.wait_group 0;" ::: "memory");
        __syncthreads();
        const int sb = (st - 1) & 1;
#pragma unroll
        for (int pl = 0; pl < 4; pl++) {
            float v[9];
#pragma unroll
            for (int ky = 0; ky < 3; ky++)
#pragma unroll
                for (int kx = 0; kx < 3; kx++)
                    v[ky * 3 + kx] = tile[sb][pl][(ty + ky) * 20 + tx + kx];
#pragma unroll
            for (int k = 0; k < 9; k++) {
                ull vv = pk2(v[k], v[k]);
#pragma unroll
                for (int p = 0; p < OCB / 2; p++)
                    fma2(acc[p], vv, *(const ull*)(&wsm[sb][pl][k * OCB + 2 * p]));
            }
        }
        __syncthreads();
    }

    float vals[OCB];
#pragma unroll
    for (int p = 0; p < OCB / 2; p++) {
        float2 o2 = up2(acc[p]);
        vals[2*p]   = fmaxf(o2.x * a.s[ocb + 2*p]     + a.bb[ocb + 2*p],     0.f);
        vals[2*p+1] = fmaxf(o2.y * a.s[ocb + 2*p + 1] + a.bb[ocb + 2*p + 1], 0.f);
    }
    if (a.mode == 0) {
#pragma unroll
        for (int j = 0; j < OCB; j++)
            a.out[(((size_t)b * 64 + ocb + j) * 64 + oy) * 64 + ox] = vals[j];
    } else if (a.mode == 1) {
        // K: [b][n][cp], pair over c
        const size_t nbase = ((size_t)b * 4096 + oy * 64 + ox) * 36 + (ocb >> 1);
#pragma unroll
        for (int p = 0; p < OCB / 2; p++) {
            u32 h = cvt2bf(vals[2*p+1], vals[2*p]);
            u32 l = cvt2bf(vals[2*p+1] - hi16f(h), vals[2*p] - lo16f(h));
            g_Khi[nbase + p] = h;
            g_Klo[nbase + p] = l;
        }
    } else {
        // V: [av*4+b][nt=oy][c][np], pair over n (adjacent lanes)
        const int lane = tid & 31;
        const int np = ox >> 1;
#pragma unroll
        for (int j = 0; j < OCB; j++) {
            float v = vals[j];
            float vp = __shfl_xor_sync(0xffffffffu, v, 1);
            if (!(lane & 1)) {
                u32 h = cvt2bf(vp, v);
                u32 l = cvt2bf(vp - hi16f(h), v - lo16f(h));
                size_t idx = (((size_t)(a.av * 4 + b) * 64 + oy) * 64 + ocb + j) * 36 + np;
                g_Vhi[idx] = h;
                g_Vlo[idx] = l;
            }
        }
    }
}

// ============================================================
// flash attention: warp mma split-bf16 x3, m-tile 128, 256 thr,
// fixed-shift softmax (valid: scores >= 0 since K,Q,V post-ReLU),
// double-buffered cp.async.  grid (32 mtiles, 4 b, 2 a)
// ============================================================
#define MMA(d, a, b0_, b1_) \
    asm volatile("mma.sync.aligned.m16n8k16.row.col.f32.bf16.bf16.f32 " \
        "{%0,%1,%2,%3}, {%4,%5,%6,%7}, {%8,%9}, {%0,%1,%2,%3};" \
        : "+f"((d)[0]), "+f"((d)[1]), "+f"((d)[2]), "+f"((d)[3]) \
        : "r"((a)[0]), "r"((a)[1]), "r"((a)[2]), "r"((a)[3]), "r"(b0_), "r"(b1_))

#define PITCH 72
#define STG_BYTES 36864u     // KH 9216 | KL 9216 | VH 9216 | VL 9216
#define QS_OFF 36864u        // Q stage overlays buffer 1
#define ATT_SMEM 73728u

__device__ __forceinline__ void fetch_chunk(u32 sbase, int tid, int nt,
        const u32* kh, const u32* kl, const u32* vh, const u32* vl) {
    const u32 off = (u32)nt * 2304u;
#pragma unroll
    for (int k = 0; k < 9; k++) {
        int idx = tid + k * 256;          // 0..2303
        int r = idx / 576, l = idx - r * 576;
        const u32* gp = (r == 0 ? kh : r == 1 ? kl : r == 2 ? vh : vl) + off + l * 4;
        asm volatile("cp.async.cg.shared.global [%0], [%1], 16;"
                     :: "r"(sbase + r * 9216u + l * 16u), "l"(gp));
    }
    asm volatile("cp.async.commit_group;" ::: "memory");
}

__global__ void __launch_bounds__(256) attn_k(const float* __restrict__ x,
                                              const float* __restrict__ y,
                                              const float* __restrict__ g1,
                                              const float* __restrict__ g2) {
    extern __shared__ char smc[];
    float* Qs = (float*)(smc + QS_OFF);
    const u32 sbA = s2u(smc);
    const int tid = threadIdx.x;
    const int w = tid >> 5, lane = tid & 31;
    const int qr = lane >> 2, qc2 = (lane & 3) * 2;
    const int m0 = blockIdx.x * 128, b = blockIdx.y, a = blockIdx.z;

    const size_t boff = (size_t)b * CH * NPIX;
    const float* Aq  = (a ? g_ik : g_rk) + boff;
    const float* res = (a ? x : y) + boff;
    float* outp      = (a ? g_ir : g_rr) + boff;
    const float gamma = a ? g2[0] : g1[0];
    const u32* kh = g_Khi + (size_t)b * 147456;
    const u32* kl = g_Klo + (size_t)b * 147456;
    const u32* vh = g_Vhi + (size_t)(a * 4 + b) * 147456;
    const u32* vl = g_Vlo + (size_t)(a * 4 + b) * 147456;

    // prefetch chunk 0 into buf0; stage Q [m][c] fp32 into buf1 region
    fetch_chunk(sbA, tid, 0, kh, kl, vh, vl);
    for (int i = tid; i < 8192; i += 256) {
        int m = i & 127, c = i >> 7;
        Qs[m * 68 + c] = Aq[(size_t)c * NPIX + m0 + m];
    }
    __syncthreads();

    // Q fragments hi/lo (row-major A)
    u32 ah[4][4], al[4][4];
    const int r0 = w * 16 + qr;
#pragma unroll
    for (int j = 0; j < 4; j++) {
        int c0 = j * 16 + qc2;
        float2 fs[4] = { *(float2*)(Qs + r0 * 68 + c0),
                         *(float2*)(Qs + (r0 + 8) * 68 + c0),
                         *(float2*)(Qs + r0 * 68 + c0 + 8),
                         *(float2*)(Qs + (r0 + 8) * 68 + c0 + 8) };
#pragma unroll
        for (int r = 0; r < 4; r++) {
            u32 h = cvt2bf(fs[r].y, fs[r].x);
            ah[j][r] = h;
            al[j][r] = cvt2bf(fs[r].y - hi16f(h), fs[r].x - lo16f(h));
        }
    }
    __syncthreads();   // Q reads done before chunk-1 prefetch overwrites Qs

    float O[8][4];
#pragma unroll
    for (int f = 0; f < 8; f++)
#pragma unroll
        for (int r = 0; r < 4; r++) O[f][r] = 0.f;
    float M0 = 0.f, M1 = 0.f, L0 = 0.f, L1 = 0.f;

    for (int nt = 0; nt < 64; nt++) {
        if (nt < 63)
            fetch_chunk(sbA + ((nt + 1) & 1) * STG_BYTES, tid, nt + 1, kh, kl, vh, vl);
        if (nt < 63) asm volatile("cp.async.wait_group 1;" ::: "memory");
        else         asm volatile("cp.async.wait_group 0;" ::: "memory");
        __syncthreads();
        const char* sbuf = smc + (nt & 1) * STG_BYTES;

        // ---- S = Q K^T, 3-term split ----
        float S[8][4];
#pragma unroll
        for (int f = 0; f < 8; f++)
#pragma unroll
            for (int r = 0; r < 4; r++) S[f][r] = 0.f;
#pragma unroll
        for (int f = 0; f < 8; f++) {
            const char* kb = sbuf + ((f * 8 + qr) * PITCH + qc2) * 2;
#pragma unroll
            for (int j = 0; j < 4; j++) {
                u32 kh0 = *(const u32*)(kb + j * 32);
                u32 kh1 = *(const u32*)(kb + j * 32 + 16);
                u32 kl0 = *(const u32*)(kb + 9216 + j * 32);
                u32 kl1 = *(const u32*)(kb + 9216 + j * 32 + 16);
                MMA(S[f], ah[j], kh0, kh1);
                MMA(S[f], al[j], kh0, kh1);
                MMA(S[f], ah[j], kl0, kl1);
            }
        }

        // ---- fixed-shift softmax: chunk 0 sets the row shift ----
        if (nt == 0) {
            float mx0 = -1e30f, mx1 = -1e30f;
#pragma unroll
            for (int f = 0; f < 8; f++) {
                mx0 = fmaxf(mx0, fmaxf(S[f][0], S[f][1]));
                mx1 = fmaxf(mx1, fmaxf(S[f][2], S[f][3]));
            }
            mx0 = fmaxf(mx0, __shfl_xor_sync(0xffffffffu, mx0, 1));
            mx0 = fmaxf(mx0, __shfl_xor_sync(0xffffffffu, mx0, 2));
            mx1 = fmaxf(mx1, __shfl_xor_sync(0xffffffffu, mx1, 1));
            mx1 = fmaxf(mx1, __shfl_xor_sync(0xffffffffu, mx1, 2));
            M0 = mx0; M1 = mx1;
        }
#pragma unroll
        for (int f = 0; f < 8; f++) {
            S[f][0] = __expf(S[f][0] - M0); S[f][1] = __expf(S[f][1] - M0);
            S[f][2] = __expf(S[f][2] - M1); S[f][3] = __expf(S[f][3] - M1);
            L0 += S[f][0] + S[f][1];
            L1 += S[f][2] + S[f][3];
        }

        // ---- O += P V^T ----
#pragma unroll
        for (int j2 = 0; j2 < 4; j2++) {
            u32 ph[4], pl2[4];
#pragma unroll
            for (int h2 = 0; h2 < 2; h2++) {
                float p0a = S[2*j2][2*h2],   p1a = S[2*j2][2*h2+1];
                float p0b = S[2*j2+1][2*h2], p1b = S[2*j2+1][2*h2+1];
                u32 hA = cvt2bf(p1a, p0a);
                u32 hB = cvt2bf(p1b, p0b);
                ph[h2]      = hA;
                ph[h2 + 2]  = hB;
                pl2[h2]     = cvt2bf(p1a - hi16f(hA), p0a - lo16f(hA));
                pl2[h2 + 2] = cvt2bf(p1b - hi16f(hB), p0b - lo16f(hB));
            }
            const char* vb = sbuf + 18432 + (qr * PITCH + j2 * 16 + qc2) * 2;
#pragma unroll
            for (int fc = 0; fc < 8; fc++) {
                u32 vh0 = *(const u32*)(vb + fc * 8 * PITCH * 2);
                u32 vh1 = *(const u32*)(vb + fc * 8 * PITCH * 2 + 16);
                u32 vl0 = *(const u32*)(vb + 9216 + fc * 8 * PITCH * 2);
                u32 vl1 = *(const u32*)(vb + 9216 + fc * 8 * PITCH * 2 + 16);
                MMA(O[fc], ph, vh0, vh1);
                MMA(O[fc], pl2, vh0, vh1);
                MMA(O[fc], ph, vl0, vl1);
            }
        }
        __syncthreads();
    }

    // ---- final L reduction (quad) + epilogue ----
    L0 += __shfl_xor_sync(0xffffffffu, L0, 1);
    L0 += __shfl_xor_sync(0xffffffffu, L0, 2);
    L1 += __shfl_xor_sync(0xffffffffu, L1, 1);
    L1 += __shfl_xor_sync(0xffffffffu, L1, 2);
    float i0 = 1.0f / L0, i1 = 1.0f / L1;
    const int mA = m0 + r0, mB = mA + 8;
#pragma unroll
    for (int fc = 0; fc < 8; fc++) {
        int c0 = fc * 8 + qc2;
        size_t iA0 = (size_t)c0 * NPIX + mA;
        size_t iA1 = (size_t)(c0 + 1) * NPIX + mA;
        outp[iA0] = gamma * (O[fc][0] * i0) + res[iA0];
        outp[iA1] = gamma * (O[fc][1] * i0) + res[iA1];
        size_t iB0 = (size_t)c0 * NPIX + mB;
        size_t iB1 = (size_t)(c0 + 1) * NPIX + mB;
        outp[iB0] = gamma * (O[fc][2] * i1) + res[iB0];
        outp[iB1] = gamma * (O[fc][3] * i1) + res[iB1];
    }
}

// ============================================================
extern "C" void kernel_launch(void* const* d_in, const int* in_sizes, int n_in,
                              void* d_out, int out_size) {
    const float* x    = (const float*)d_in[0];
    const float* y    = (const float*)d_in[1];
    const float* q_w  = (const float*)d_in[2];
    const float* q_s  = (const float*)d_in[3];
    const float* q_b  = (const float*)d_in[4];
    const float* rk_w = (const float*)d_in[5];
    const float* rk_s = (const float*)d_in[6];
    const float* rk_b = (const float*)d_in[7];
    const float* rv_w = (const float*)d_in[8];
    const float* rv_s = (const float*)d_in[9];
    const float* rv_b = (const float*)d_in[10];
    const float* ik_w = (const float*)d_in[11];
    const float* ik_s = (const float*)d_in[12];
    const float* ik_b = (const float*)d_in[13];
    const float* iv_w = (const float*)d_in[14];
    const float* iv_s = (const float*)d_in[15];
    const float* iv_b = (const float*)d_in[16];
    const float* sr_w = (const float*)d_in[17];
    const float* sr_s = (const float*)d_in[18];
    const float* sr_b = (const float*)d_in[19];
    const float* g1   = (const float*)d_in[20];
    const float* g2   = (const float*)d_in[21];
    float* out = (float*)d_out;

    float *prk, *pik, *prr, *pir;
    cudaGetSymbolAddress((void**)&prk, g_rk);
    cudaGetSymbolAddress((void**)&pik, g_ik);
    cudaGetSymbolAddress((void**)&prr, g_rr);
    cudaGetSymbolAddress((void**)&pir, g_ir);

    cudaFuncSetAttribute(attn_k, cudaFuncAttributeMaxDynamicSharedMemorySize,
                         (int)ATT_SMEM);

    // producers (16 oc/block): Q conv -> K split (mode 1),
    // rk/ik -> fp32 (mode 0), rv/iv -> V split (mode 2)
    CPack pp = {};
    pp.c[0] = { x, y,       q_w,  q_s,  q_b,  nullptr, 128, 1, 0 };
    pp.c[1] = { x, nullptr, rk_w, rk_s, rk_b, prk,      64, 0, 0 };
    pp.c[2] = { x, nullptr, rv_w, rv_s, rv_b, nullptr,  64, 2, 0 };
    pp.c[3] = { y, nullptr, ik_w, ik_s, ik_b, pik,      64, 0, 0 };
    pp.c[4] = { y, nullptr, iv_w, iv_s, iv_b, nullptr,  64, 2, 1 };
    conv_k<16><<<dim3(4, 4, 80), 256>>>(pp);

    attn_k<<<dim3(32, 4, 2), 256, ATT_SMEM>>>(x, y, g1, g2);

    // final conv (8 oc/block for grid occupancy)
    CPack ps = {};
    ps.c[0] = { prr, pir, sr_w, sr_s, sr_b, out, 128, 0, 0 };
    conv_k<8><<<dim3(4, 4, 32), 256>>>(ps);
}